// round 15
// baseline (speedup 1.0000x reference)
#include <cuda_runtime.h>
#include <cuda_bf16.h>
#include <cstdint>
#include <cstddef>

#define N_NODES     100000
#define N_EDGES     800000
#define F           128
#define NUM_GRAPHS  128
#define NUM_CLASSES 10
#define BN_EPS      1e-5f

#define SCAN_BLK 1024
#define SCAN_NB  ((N_NODES + SCAN_BLK - 1) / SCAN_BLK)   // 98

// ---------------- scratch (static device globals; no allocation) ----------------
__device__ float g_bufA[(size_t)N_NODES * F];   // 51.2 MB
__device__ float g_bufB[(size_t)N_NODES * F];   // 51.2 MB
__device__ float g_bufC[(size_t)N_NODES * F];   // 51.2 MB
__device__ float g_sum1[F];
__device__ float g_sq1[F];
__device__ float g_sum2[F];
__device__ float g_sq2[F];
__device__ float g_scale1[F];
__device__ float g_shift1[F];
__device__ float g_scale2[F];
__device__ float g_shift2[F];
__device__ float g_pooled[NUM_GRAPHS * F];
__device__ float g_counts[NUM_GRAPHS];
// packed bf16 mma B-fragments: per (matrix, kt*16+nt, lane) one uint4 {h0,h1,l0,l1}
__device__ uint4 g_wtabP[4][4096];
// CSR-by-destination edge structure (rebuilt every launch)
// g_hist starts zeroed (static init) and is re-zeroed by scan1 every replay.
__device__ int g_hist[N_NODES];
__device__ int g_off[N_NODES + 1];
__device__ int g_cursor[N_NODES];
__device__ int g_esrc[N_EDGES];
__device__ int g_blocksum[SCAN_NB];

// ---------------- zero the small accumulators (every replay) --------------------
__global__ void zero_small_kernel() {
    int t = blockIdx.x * blockDim.x + threadIdx.x;
    if (t < F) {
        g_sum1[t] = 0.f; g_sq1[t] = 0.f;
        g_sum2[t] = 0.f; g_sq2[t] = 0.f;
    }
    if (t < NUM_GRAPHS) g_counts[t] = 0.f;
    for (int i = t; i < NUM_GRAPHS * F; i += blockDim.x * gridDim.x)
        g_pooled[i] = 0.f;
}

// ---------------- CSR build: histogram -> scan (2 kernels) -> reorder -----------
__global__ void hist_kernel(const int* __restrict__ ei) {
    int e = blockIdx.x * blockDim.x + threadIdx.x;
    if (e < N_EDGES) atomicAdd(&g_hist[ei[N_EDGES + e]], 1);
}

// phase 1: block-local exclusive scan of 1024 counters + block total.
// Also re-zeroes g_hist for the next replay (no memset launch needed).
__global__ void scan1_kernel() {
    __shared__ int sdata[SCAN_BLK];
    int t   = threadIdx.x;
    int gid = blockIdx.x * SCAN_BLK + t;
    int v = 0;
    if (gid < N_NODES) {
        v = g_hist[gid];
        g_hist[gid] = 0;          // reset for next replay
    }
    sdata[t] = v;
    __syncthreads();
    for (int o = 1; o < SCAN_BLK; o <<= 1) {
        int u = (t >= o) ? sdata[t - o] : 0;
        __syncthreads();
        sdata[t] += u;
        __syncthreads();
    }
    if (gid < N_NODES) g_off[gid] = sdata[t] - v;   // exclusive within block
    if (t == SCAN_BLK - 1) g_blocksum[blockIdx.x] = sdata[t];
}

// phase 2+3 fused: each block scans the 98 block sums in smem (redundant,
// trivial), then adds its prefix, inits cursors, sets sentinel.
__global__ void scan3_kernel() {
    __shared__ int s[128];
    int t = threadIdx.x;
    if (t < 128) {
        int v = (t < SCAN_NB) ? g_blocksum[t] : 0;
        s[t] = v;
    }
    __syncthreads();
    // 128-wide inclusive scan done by first 128 threads
    if (t < 128) {
        for (int o = 1; o < 128; o <<= 1) {
            int u = (t >= o) ? s[t - o] : 0;
            __syncthreads();
            s[t] += u;
            __syncthreads();
        }
    } else {
        for (int o = 1; o < 128; o <<= 1) { __syncthreads(); __syncthreads(); }
    }
    __syncthreads();
    int blockPrefix = (blockIdx.x == 0) ? 0 : s[blockIdx.x - 1];
    int gid = blockIdx.x * SCAN_BLK + t;
    if (gid < N_NODES) {
        int o = g_off[gid] + blockPrefix;
        g_off[gid] = o;
        g_cursor[gid] = o;
    }
    if (gid == 0) g_off[N_NODES] = N_EDGES;
}

__global__ void reorder_kernel(const int* __restrict__ ei) {
    int e = blockIdx.x * blockDim.x + threadIdx.x;
    if (e >= N_EDGES) return;
    int s = ei[e];
    int d = ei[N_EDGES + e];
    int pos = atomicAdd(&g_cursor[d], 1);
    g_esrc[pos] = s;
}

// ---------------- atomic-free aggregation: warp per node ------------------------
// Streaming stores for output + streaming loads for esrc keep X (the 8x-reused
// gather table) as the sole cached tenant in L2.
template <bool BN>
__global__ void __launch_bounds__(256)
agg_kernel(const float* __restrict__ X, float* __restrict__ out,
           const float* __restrict__ scale, const float* __restrict__ shift) {
    int node = blockIdx.x * 8 + (threadIdx.x >> 5);
    int lane = threadIdx.x & 31;
    if (node >= N_NODES) return;
    int b0 = g_off[node], b1 = g_off[node + 1];
    float4 sc, sh;
    if (BN) {
        sc = reinterpret_cast<const float4*>(scale)[lane];   // L1-resident
        sh = reinterpret_cast<const float4*>(shift)[lane];
    }
    float4 a0 = make_float4(0.f, 0.f, 0.f, 0.f);
    float4 a1 = a0, a2 = a0, a3 = a0;

    int i = b0;
    for (; i + 4 <= b1; i += 4) {
        int s0 = __ldcs(&g_esrc[i]);
        int s1 = __ldcs(&g_esrc[i + 1]);
        int s2 = __ldcs(&g_esrc[i + 2]);
        int s3 = __ldcs(&g_esrc[i + 3]);
        float4 v0 = reinterpret_cast<const float4*>(X + (size_t)s0 * F)[lane];
        float4 v1 = reinterpret_cast<const float4*>(X + (size_t)s1 * F)[lane];
        float4 v2 = reinterpret_cast<const float4*>(X + (size_t)s2 * F)[lane];
        float4 v3 = reinterpret_cast<const float4*>(X + (size_t)s3 * F)[lane];
        if (BN) {
            v0.x = fmaxf(v0.x * sc.x + sh.x, 0.f); v0.y = fmaxf(v0.y * sc.y + sh.y, 0.f);
            v0.z = fmaxf(v0.z * sc.z + sh.z, 0.f); v0.w = fmaxf(v0.w * sc.w + sh.w, 0.f);
            v1.x = fmaxf(v1.x * sc.x + sh.x, 0.f); v1.y = fmaxf(v1.y * sc.y + sh.y, 0.f);
            v1.z = fmaxf(v1.z * sc.z + sh.z, 0.f); v1.w = fmaxf(v1.w * sc.w + sh.w, 0.f);
            v2.x = fmaxf(v2.x * sc.x + sh.x, 0.f); v2.y = fmaxf(v2.y * sc.y + sh.y, 0.f);
            v2.z = fmaxf(v2.z * sc.z + sh.z, 0.f); v2.w = fmaxf(v2.w * sc.w + sh.w, 0.f);
            v3.x = fmaxf(v3.x * sc.x + sh.x, 0.f); v3.y = fmaxf(v3.y * sc.y + sh.y, 0.f);
            v3.z = fmaxf(v3.z * sc.z + sh.z, 0.f); v3.w = fmaxf(v3.w * sc.w + sh.w, 0.f);
        }
        a0.x += v0.x; a0.y += v0.y; a0.z += v0.z; a0.w += v0.w;
        a1.x += v1.x; a1.y += v1.y; a1.z += v1.z; a1.w += v1.w;
        a2.x += v2.x; a2.y += v2.y; a2.z += v2.z; a2.w += v2.w;
        a3.x += v3.x; a3.y += v3.y; a3.z += v3.z; a3.w += v3.w;
    }
    for (; i < b1; i++) {
        int s = __ldcs(&g_esrc[i]);
        float4 v = reinterpret_cast<const float4*>(X + (size_t)s * F)[lane];
        if (BN) {
            v.x = fmaxf(v.x * sc.x + sh.x, 0.f);
            v.y = fmaxf(v.y * sc.y + sh.y, 0.f);
            v.z = fmaxf(v.z * sc.z + sh.z, 0.f);
            v.w = fmaxf(v.w * sc.w + sh.w, 0.f);
        }
        a0.x += v.x; a0.y += v.y; a0.z += v.z; a0.w += v.w;
    }
    a0.x += a1.x + a2.x + a3.x;
    a0.y += a1.y + a2.y + a3.y;
    a0.z += a1.z + a2.z + a3.z;
    a0.w += a1.w + a2.w + a3.w;
    __stcs(reinterpret_cast<float4*>(out + (size_t)node * F) + lane, a0);
}

// ---------------- bf16 split helpers -------------------------------------------
__device__ __forceinline__ uint32_t pk2(__nv_bfloat16 a, __nv_bfloat16 b) {
    return (uint32_t)__bfloat16_as_ushort(b) << 16 | (uint32_t)__bfloat16_as_ushort(a);
}
__device__ __forceinline__ void split_pair(float x, float y,
                                           uint32_t& hi, uint32_t& lo) {
    __nv_bfloat16 hx = __float2bfloat16_rn(x);
    __nv_bfloat16 hy = __float2bfloat16_rn(y);
    float rx = x - __bfloat162float(hx);
    float ry = y - __bfloat162float(hy);
    hi = pk2(hx, hy);
    lo = pk2(__float2bfloat16_rn(rx), __float2bfloat16_rn(ry));
}

// ---------------- prep: pack all 4 W matrices into packed uint4 fragment tables -
__global__ void prep_w_all_kernel(const float* __restrict__ Wa,
                                  const float* __restrict__ Wb,
                                  const float* __restrict__ Wc,
                                  const float* __restrict__ Wd) {
    int gid   = blockIdx.x * blockDim.x + threadIdx.x;   // 0..16383
    int which = gid >> 12;
    int tid   = gid & 4095;
    const float* W = which == 0 ? Wa : which == 1 ? Wb : which == 2 ? Wc : Wd;
    int lane = tid & 31;
    int e    = tid >> 5;
    int nt   = e & 15;
    int kt   = e >> 4;
    int n  = nt * 8 + (lane >> 2);
    int k0 = kt * 16 + (lane & 3) * 2;
    uint32_t h0, l0, h1, l1;
    split_pair(W[k0 * 128 + n],       W[(k0 + 1) * 128 + n], h0, l0);
    split_pair(W[(k0 + 8) * 128 + n], W[(k0 + 9) * 128 + n], h1, l1);
    g_wtabP[which][tid] = make_uint4(h0, h1, l0, l1);
}

// ---------------- mma wrapper ---------------------------------------------------
__device__ __forceinline__ void mma_bf16(float c[4],
                                         uint32_t a0, uint32_t a1, uint32_t a2, uint32_t a3,
                                         uint32_t b0, uint32_t b1) {
    asm volatile(
        "mma.sync.aligned.m16n8k16.row.col.f32.bf16.bf16.f32 "
        "{%0,%1,%2,%3}, {%4,%5,%6,%7}, {%8,%9}, {%0,%1,%2,%3};"
        : "+f"(c[0]), "+f"(c[1]), "+f"(c[2]), "+f"(c[3])
        : "r"(a0), "r"(a1), "r"(a2), "r"(a3), "r"(b0), "r"(b1));
}

// ---------------- fused MLP (unchanged) -----------------------------------------
#define SA 68   // smem row stride in 32-bit words
#define MLP_SMEM (2 * 128 * SA * 4 + 256 * 4)   // A tiles + 256-float stats region
__global__ void __launch_bounds__(256, 2)
mlp_kernel(const float* __restrict__ Ain, const float* __restrict__ addSrc,
           const float* __restrict__ bnScale, const float* __restrict__ bnShift,
           float* __restrict__ C,
           const uint4* __restrict__ t1p, const uint4* __restrict__ t2p,
           const float* __restrict__ bias1, const float* __restrict__ bias2,
           float* __restrict__ gsum, float* __restrict__ gsq,
           int M) {
    extern __shared__ uint32_t sm[];
    uint32_t* Ahi = sm;                 // 128 * 68 words
    uint32_t* Alo = sm + 128 * SA;
    float*    Ssm = reinterpret_cast<float*>(sm + 2 * 128 * SA);  // [128] sums
    float*    Qsm = Ssm + 128;                                    // [128] sqs

    const int t    = threadIdx.x;
    const int lane = t & 31;
    const int w    = t >> 5;
    const int base = blockIdx.x * 128;

    if (t < 256) { Ssm[t] = 0.f; }   // zeros both Ssm and Qsm (256 contiguous)

    // ---- stage A tile: (Ain + addSrc[BN]) fp32 -> bf16 hi/lo smem --------------
    {
        int r    = t >> 1;            // row 0..127
        int half = t & 1;             // 64-col half
        int grow = base + r;
        bool valid = grow < M;
        const float4* src = valid
            ? reinterpret_cast<const float4*>(Ain + (size_t)grow * 128 + half * 64)
            : nullptr;
        const float4* add = valid
            ? reinterpret_cast<const float4*>(addSrc + (size_t)grow * 128 + half * 64)
            : nullptr;
        const float4* sc4 = bnScale
            ? reinterpret_cast<const float4*>(bnScale) + half * 16 : nullptr;
        const float4* sh4 = bnShift
            ? reinterpret_cast<const float4*>(bnShift) + half * 16 : nullptr;
        uint32_t* dh = Ahi + r * SA + half * 32;
        uint32_t* dl = Alo + r * SA + half * 32;
#pragma unroll
        for (int i = 0; i < 16; i++) {
            float4 v = make_float4(0.f, 0.f, 0.f, 0.f);
            if (valid) {
                float4 s = src[i];
                float4 a = add[i];
                if (sc4) {
                    float4 sc = sc4[i], sh = sh4[i];
                    a.x = fmaxf(a.x * sc.x + sh.x, 0.f);
                    a.y = fmaxf(a.y * sc.y + sh.y, 0.f);
                    a.z = fmaxf(a.z * sc.z + sh.z, 0.f);
                    a.w = fmaxf(a.w * sc.w + sh.w, 0.f);
                }
                v = make_float4(s.x + a.x, s.y + a.y, s.z + a.z, s.w + a.w);
            }
            uint32_t h0, l0, h1, l1;
            split_pair(v.x, v.y, h0, l0);
            split_pair(v.z, v.w, h1, l1);
            *reinterpret_cast<uint2*>(&dh[i * 2]) = make_uint2(h0, h1);
            *reinterpret_cast<uint2*>(&dl[i * 2]) = make_uint2(l0, l1);
        }
    }
    __syncthreads();

    const int g      = w >> 1;              // row group 0..3
    const int ntBase = (w & 1) * 8;         // column half
    const int mBase  = g * 32;
    const int ar0    = (mBase + (lane >> 2)) * SA + (lane & 3);  // rowtile 0 frag base
    const int ar1    = ar0 + 16 * SA;                            // rowtile 1

    float acc0[8][4], acc1[8][4];
#pragma unroll
    for (int nt = 0; nt < 8; nt++)
#pragma unroll
        for (int i = 0; i < 4; i++) { acc0[nt][i] = 0.f; acc1[nt][i] = 0.f; }

    // ================= GEMM 1 =================
#pragma unroll
    for (int kt = 0; kt < 8; kt++) {
        int wp0 = ar0 + kt * 8;
        int wp1 = ar1 + kt * 8;
        uint32_t xh0 = Ahi[wp0],     xh1 = Ahi[wp0 + 8 * SA];
        uint32_t xh2 = Ahi[wp0 + 4], xh3 = Ahi[wp0 + 8 * SA + 4];
        uint32_t xl0 = Alo[wp0],     xl1 = Alo[wp0 + 8 * SA];
        uint32_t xl2 = Alo[wp0 + 4], xl3 = Alo[wp0 + 8 * SA + 4];
        uint32_t yh0 = Ahi[wp1],     yh1 = Ahi[wp1 + 8 * SA];
        uint32_t yh2 = Ahi[wp1 + 4], yh3 = Ahi[wp1 + 8 * SA + 4];
        uint32_t yl0 = Alo[wp1],     yl1 = Alo[wp1 + 8 * SA];
        uint32_t yl2 = Alo[wp1 + 4], yl3 = Alo[wp1 + 8 * SA + 4];
#pragma unroll
        for (int nt = 0; nt < 8; nt++) {
            uint4 b = t1p[(kt * 16 + ntBase + nt) * 32 + lane];
            mma_bf16(acc0[nt], xh0, xh1, xh2, xh3, b.x, b.y);   // hi*hi
            mma_bf16(acc1[nt], yh0, yh1, yh2, yh3, b.x, b.y);
            mma_bf16(acc0[nt], xh0, xh1, xh2, xh3, b.z, b.w);   // hi*lo
            mma_bf16(acc1[nt], yh0, yh1, yh2, yh3, b.z, b.w);
            mma_bf16(acc0[nt], xl0, xl1, xl2, xl3, b.x, b.y);   // lo*hi
            mma_bf16(acc1[nt], yl0, yl1, yl2, yl3, b.x, b.y);
        }
    }
    __syncthreads();

    // ---- mid epilogue: bias1 + relu, re-split t1 into the same smem tile ----
#pragma unroll
    for (int nt = 0; nt < 8; nt++) {
        int ntg = ntBase + nt;
        int n0  = ntg * 8 + (lane & 3) * 2;
        float bb0 = bias1[n0], bb1 = bias1[n0 + 1];
        int word0 = (mBase + (lane >> 2)) * SA + ntg * 4 + (lane & 3);
#pragma unroll
        for (int rt = 0; rt < 2; rt++) {
            float (&a)[4] = rt ? acc1[nt] : acc0[nt];
            int word = word0 + rt * 16 * SA;
            float v0 = fmaxf(a[0] + bb0, 0.f);
            float v1 = fmaxf(a[1] + bb1, 0.f);
            float v2 = fmaxf(a[2] + bb0, 0.f);
            float v3 = fmaxf(a[3] + bb1, 0.f);
            uint32_t h, l;
            split_pair(v0, v1, h, l);
            Ahi[word] = h;  Alo[word] = l;
            split_pair(v2, v3, h, l);
            Ahi[word + 8 * SA] = h;  Alo[word + 8 * SA] = l;
            a[0] = a[1] = a[2] = a[3] = 0.f;
        }
    }
    __syncthreads();

    // ================= GEMM 2 =================
#pragma unroll
    for (int kt = 0; kt < 8; kt++) {
        int wp0 = ar0 + kt * 8;
        int wp1 = ar1 + kt * 8;
        uint32_t xh0 = Ahi[wp0],     xh1 = Ahi[wp0 + 8 * SA];
        uint32_t xh2 = Ahi[wp0 + 4], xh3 = Ahi[wp0 + 8 * SA + 4];
        uint32_t xl0 = Alo[wp0],     xl1 = Alo[wp0 + 8 * SA];
        uint32_t xl2 = Alo[wp0 + 4], xl3 = Alo[wp0 + 8 * SA + 4];
        uint32_t yh0 = Ahi[wp1],     yh1 = Ahi[wp1 + 8 * SA];
        uint32_t yh2 = Ahi[wp1 + 4], yh3 = Ahi[wp1 + 8 * SA + 4];
        uint32_t yl0 = Alo[wp1],     yl1 = Alo[wp1 + 8 * SA];
        uint32_t yl2 = Alo[wp1 + 4], yl3 = Alo[wp1 + 8 * SA + 4];
#pragma unroll
        for (int nt = 0; nt < 8; nt++) {
            uint4 b = t2p[(kt * 16 + ntBase + nt) * 32 + lane];
            mma_bf16(acc0[nt], xh0, xh1, xh2, xh3, b.x, b.y);
            mma_bf16(acc1[nt], yh0, yh1, yh2, yh3, b.x, b.y);
            mma_bf16(acc0[nt], xh0, xh1, xh2, xh3, b.z, b.w);
            mma_bf16(acc1[nt], yh0, yh1, yh2, yh3, b.z, b.w);
            mma_bf16(acc0[nt], xl0, xl1, xl2, xl3, b.x, b.y);
            mma_bf16(acc1[nt], yl0, yl1, yl2, yl3, b.x, b.y);
        }
    }

    // ---- final epilogue: bias2, fp32 store, fused per-column BN statistics ----
#pragma unroll
    for (int nt = 0; nt < 8; nt++) {
        int ntg = ntBase + nt;
        int n0  = ntg * 8 + (lane & 3) * 2;
        float bb0 = bias2[n0], bb1 = bias2[n0 + 1];
        float S0 = 0.f, S1 = 0.f, Q0 = 0.f, Q1 = 0.f;
#pragma unroll
        for (int rt = 0; rt < 2; rt++) {
            float (&a)[4] = rt ? acc1[nt] : acc0[nt];
            int row0 = base + mBase + rt * 16 + (lane >> 2);
            bool r0v = row0 < M, r1v = (row0 + 8) < M;
            float v0 = a[0] + bb0, v1 = a[1] + bb1;
            float v2 = a[2] + bb0, v3 = a[3] + bb1;
            if (r0v)
                *reinterpret_cast<float2*>(C + (size_t)row0 * 128 + n0) = make_float2(v0, v1);
            if (r1v)
                *reinterpret_cast<float2*>(C + (size_t)(row0 + 8) * 128 + n0) = make_float2(v2, v3);
            S0 += (r0v ? v0 : 0.f) + (r1v ? v2 : 0.f);
            S1 += (r0v ? v1 : 0.f) + (r1v ? v3 : 0.f);
            Q0 += (r0v ? v0 * v0 : 0.f) + (r1v ? v2 * v2 : 0.f);
            Q1 += (r0v ? v1 * v1 : 0.f) + (r1v ? v3 * v3 : 0.f);
        }
#pragma unroll
        for (int o = 4; o < 32; o <<= 1) {
            S0 += __shfl_xor_sync(0xffffffffu, S0, o);
            S1 += __shfl_xor_sync(0xffffffffu, S1, o);
            Q0 += __shfl_xor_sync(0xffffffffu, Q0, o);
            Q1 += __shfl_xor_sync(0xffffffffu, Q1, o);
        }
        if ((lane >> 2) == 0) {   // lanes 0..3, distinct n0 per lane
            atomicAdd(&Ssm[n0], S0);     atomicAdd(&Ssm[n0 + 1], S1);
            atomicAdd(&Qsm[n0], Q0);     atomicAdd(&Qsm[n0 + 1], Q1);
        }
    }
    __syncthreads();
    if (t < 128) {
        atomicAdd(&gsum[t], Ssm[t]);
        atomicAdd(&gsq[t],  Qsm[t]);
    }
}

// ---------------- BN coefficient computation (1 block, 128 threads) -------------
__global__ void bn_coef_kernel(const float* __restrict__ sum,
                               const float* __restrict__ sq,
                               const float* __restrict__ gamma,
                               const float* __restrict__ beta,
                               float* __restrict__ scale,
                               float* __restrict__ shift) {
    int c = threadIdx.x;
    const float invN = 1.0f / (float)N_NODES;
    float mean = sum[c] * invN;
    float var  = fmaxf(sq[c] * invN - mean * mean, 0.f);
    float sc   = gamma[c] * rsqrtf(var + BN_EPS);
    scale[c] = sc;
    shift[c] = beta[c] - mean * sc;
}

// ---------------- fused BN2 + ReLU + segmented pool + counts (batch sorted) -----
#define POOL_CHUNK 512
__global__ void pool_kernel(const float* __restrict__ H,
                            const float* __restrict__ scale,
                            const float* __restrict__ shift,
                            const int* __restrict__ batch) {
    const int c = threadIdx.x;   // blockDim = 128
    float sc = scale[c], sh = shift[c];

    int r0 = blockIdx.x * POOL_CHUNK;
    if (r0 >= N_NODES) return;
    int r1 = min(r0 + POOL_CHUNK, N_NODES);

    int g = batch[r0];
    float acc = 0.f;
    int cnt = 0;
    for (int r = r0; r < r1; r++) {
        int gg = batch[r];
        if (gg != g) {
            atomicAdd(&g_pooled[g * F + c], acc);
            if (c == 0) atomicAdd(&g_counts[g], (float)cnt);
            acc = 0.f; cnt = 0; g = gg;
        }
        acc += fmaxf(H[(size_t)r * F + c] * sc + sh, 0.f);
        cnt++;
    }
    atomicAdd(&g_pooled[g * F + c], acc);
    if (c == 0) atomicAdd(&g_counts[g], (float)cnt);
}

// ---------------- head: mean-pool divide + linear + log_softmax ----------------
__global__ void head_kernel(const float* __restrict__ Wlin,
                            const float* __restrict__ blin,
                            float* __restrict__ out) {
    __shared__ float Ws[F * NUM_CLASSES];
    int t = threadIdx.x;   // blockDim = 128, one thread per graph
    for (int i = t; i < F * NUM_CLASSES; i += 128) Ws[i] = Wlin[i];
    __syncthreads();

    int g = t;
    float inv = 1.0f / fmaxf(g_counts[g], 1.0f);
    float logit[NUM_CLASSES];
#pragma unroll
    for (int j = 0; j < NUM_CLASSES; j++) logit[j] = blin[j];
    for (int c = 0; c < F; c++) {
        float p = g_pooled[g * F + c] * inv;
#pragma unroll
        for (int j = 0; j < NUM_CLASSES; j++)
            logit[j] += p * Ws[c * NUM_CLASSES + j];
    }
    float m = logit[0];
#pragma unroll
    for (int j = 1; j < NUM_CLASSES; j++) m = fmaxf(m, logit[j]);
    float se = 0.f;
#pragma unroll
    for (int j = 0; j < NUM_CLASSES; j++) se += expf(logit[j] - m);
    float lse = logf(se);
#pragma unroll
    for (int j = 0; j < NUM_CLASSES; j++)
        out[g * NUM_CLASSES + j] = logit[j] - m - lse;
}

// ================================================================================
extern "C" void kernel_launch(void* const* d_in, const int* in_sizes, int n_in,
                              void* d_out, int out_size) {
    const float* x     = (const float*)d_in[0];
    const int*   ei    = (const int*)d_in[1];
    const int*   batch = (const int*)d_in[2];
    const float* W1a = (const float*)d_in[3];
    const float* b1a = (const float*)d_in[4];
    const float* W1b = (const float*)d_in[5];
    const float* b1b = (const float*)d_in[6];
    const float* gamma1 = (const float*)d_in[7];
    const float* beta1  = (const float*)d_in[8];
    const float* W2a = (const float*)d_in[9];
    const float* b2a = (const float*)d_in[10];
    const float* W2b = (const float*)d_in[11];
    const float* b2b = (const float*)d_in[12];
    const float* gamma2 = (const float*)d_in[13];
    const float* beta2  = (const float*)d_in[14];
    const float* Wlin = (const float*)d_in[15];
    const float* blin = (const float*)d_in[16];
    float* out = (float*)d_out;

    float *pA, *pB, *pC, *pSum1, *pSq1, *pSum2, *pSq2;
    float *pScale1, *pShift1, *pScale2, *pShift2;
    uint4 *pWP;
    cudaGetSymbolAddress((void**)&pA, g_bufA);
    cudaGetSymbolAddress((void**)&pB, g_bufB);
    cudaGetSymbolAddress((void**)&pC, g_bufC);
    cudaGetSymbolAddress((void**)&pSum1, g_sum1);
    cudaGetSymbolAddress((void**)&pSq1,  g_sq1);
    cudaGetSymbolAddress((void**)&pSum2, g_sum2);
    cudaGetSymbolAddress((void**)&pSq2,  g_sq2);
    cudaGetSymbolAddress((void**)&pScale1, g_scale1);
    cudaGetSymbolAddress((void**)&pShift1, g_shift1);
    cudaGetSymbolAddress((void**)&pScale2, g_scale2);
    cudaGetSymbolAddress((void**)&pShift2, g_shift2);
    cudaGetSymbolAddress((void**)&pWP, g_wtabP);

    static int smem_set = 0;
    if (!smem_set) {
        cudaFuncSetAttribute(mlp_kernel,
                             cudaFuncAttributeMaxDynamicSharedMemorySize, MLP_SMEM);
        smem_set = 1;
    }

    const int M = N_NODES;
    const int mlpBlocks = (M + 127) / 128;
    const int edgeBlocks = (N_EDGES + 255) / 256;
    const int aggBlocks = (N_NODES + 7) / 8;

    // build CSR-by-destination (g_hist pre-zeroed: static init + scan1 re-zero)
    hist_kernel<<<edgeBlocks, 256>>>(ei);                  // launch 1
    scan1_kernel<<<SCAN_NB, SCAN_BLK>>>();                 // launch 2 (zeroes hist)
    scan3_kernel<<<SCAN_NB, SCAN_BLK>>>();                 // launch 3 (scan2 fused)
    reorder_kernel<<<edgeBlocks, 256>>>(ei);               // launch 4

    // ---- layer 1: agg1 = sum_neighbors(x) -> bufA (launch 5: ncu-captured)
    agg_kernel<false><<<aggBlocks, 256>>>(x, pA, nullptr, nullptr);

    // prep: zero accumulators + pack weight tables (before mlp1)
    zero_small_kernel<<<64, 256>>>();
    prep_w_all_kernel<<<64, 256>>>(W1a, W1b, W2a, W2b);

    // MLP1 adds +x during staging
    mlp_kernel<<<mlpBlocks, 256, MLP_SMEM>>>(
        pA, x, nullptr, nullptr, pA,
        pWP + 0 * 4096, pWP + 1 * 4096,
        b1a, b1b, pSum1, pSq1, M);
    bn_coef_kernel<<<1, 128>>>(pSum1, pSq1, gamma1, beta1, pScale1, pShift1);

    // ---- layer 2: agg2 = sum_neighbors(BN1(h1)) -> bufC ; MLP2 adds +BN1(h1)
    agg_kernel<true><<<aggBlocks, 256>>>(pA, pC, pScale1, pShift1);
    mlp_kernel<<<mlpBlocks, 256, MLP_SMEM>>>(
        pC, pA, pScale1, pShift1, pB,
        pWP + 2 * 4096, pWP + 3 * 4096,
        b2a, b2b, pSum2, pSq2, M);
    bn_coef_kernel<<<1, 128>>>(pSum2, pSq2, gamma2, beta2, pScale2, pShift2);

    // ---- pooling (BN2+ReLU on the fly, fused counts) + head
    pool_kernel<<<(N_NODES + POOL_CHUNK - 1) / POOL_CHUNK, 128>>>(
        pB, pScale2, pShift2, batch);
    head_kernel<<<1, 128>>>(Wlin, blin, out);
}

// round 16
// speedup vs baseline: 1.2466x; 1.2466x over previous
#include <cuda_runtime.h>
#include <cuda_bf16.h>
#include <cstdint>
#include <cstddef>

#define N_NODES     100000
#define N_EDGES     800000
#define F           128
#define NUM_GRAPHS  128
#define NUM_CLASSES 10
#define BN_EPS      1e-5f

#define SCAN_BLK 1024
#define SCAN_NB  ((N_NODES + SCAN_BLK - 1) / SCAN_BLK)   // 98

// ---------------- scratch (static device globals; no allocation) ----------------
__device__ float g_bufA[(size_t)N_NODES * F];   // 51.2 MB
__device__ float g_bufB[(size_t)N_NODES * F];   // 51.2 MB
__device__ float g_bufC[(size_t)N_NODES * F];   // 51.2 MB
__device__ float g_sum1[F];
__device__ float g_sq1[F];
__device__ float g_sum2[F];
__device__ float g_sq2[F];
__device__ float g_scale1[F];
__device__ float g_shift1[F];
__device__ float g_scale2[F];
__device__ float g_shift2[F];
__device__ float g_pooled[NUM_GRAPHS * F];
__device__ float g_counts[NUM_GRAPHS];
// packed bf16 mma B-fragments: per (matrix, kt*16+nt, lane) one uint4 {h0,h1,l0,l1}
__device__ uint4 g_wtabP[4][4096];
// CSR-by-destination edge structure (rebuilt every launch)
// g_hist starts zeroed (static init) and is re-zeroed by scanF every replay.
__device__ int g_hist[N_NODES];
__device__ int g_off[N_NODES];     // bucket start (arrival-ordered partition)
__device__ int g_end[N_NODES];     // bucket end
__device__ int g_cursor[N_NODES];
__device__ int g_esrc[N_EDGES];
__device__ int g_gcnt;             // global bucket allocator (reset by hist)

// ---------------- zero the small accumulators (every replay) --------------------
__global__ void zero_small_kernel() {
    int t = blockIdx.x * blockDim.x + threadIdx.x;
    if (t < F) {
        g_sum1[t] = 0.f; g_sq1[t] = 0.f;
        g_sum2[t] = 0.f; g_sq2[t] = 0.f;
    }
    if (t < NUM_GRAPHS) g_counts[t] = 0.f;
    for (int i = t; i < NUM_GRAPHS * F; i += blockDim.x * gridDim.x)
        g_pooled[i] = 0.f;
}

// ---------------- CSR build: histogram -> fused scan -> reorder -----------------
__global__ void hist_kernel(const int* __restrict__ ei) {
    if (blockIdx.x == 0 && threadIdx.x == 0) g_gcnt = 0;   // reset allocator
    int e = blockIdx.x * blockDim.x + threadIdx.x;
    if (e < N_EDGES) atomicAdd(&g_hist[ei[N_EDGES + e]], 1);
}

// Fused scan: block-local scan; block prefix allocated via atomicAdd in arrival
// order (bucket layout is an arbitrary disjoint partition of [0, N_EDGES) -- no
// sortedness needed since g_end is stored explicitly). Also re-zeroes g_hist.
__global__ void scanF_kernel() {
    __shared__ int sdata[SCAN_BLK];
    __shared__ int sbase;
    int t   = threadIdx.x;
    int gid = blockIdx.x * SCAN_BLK + t;
    int v = 0;
    if (gid < N_NODES) {
        v = g_hist[gid];
        g_hist[gid] = 0;          // reset for next replay
    }
    sdata[t] = v;
    __syncthreads();
    for (int o = 1; o < SCAN_BLK; o <<= 1) {
        int u = (t >= o) ? sdata[t - o] : 0;
        __syncthreads();
        sdata[t] += u;
        __syncthreads();
    }
    if (t == SCAN_BLK - 1) sbase = atomicAdd(&g_gcnt, sdata[t]);
    __syncthreads();
    if (gid < N_NODES) {
        int o = sbase + sdata[t] - v;   // exclusive prefix within arrival order
        g_off[gid]    = o;
        g_cursor[gid] = o;
        g_end[gid]    = o + v;
    }
}

__global__ void reorder_kernel(const int* __restrict__ ei) {
    int e = blockIdx.x * blockDim.x + threadIdx.x;
    if (e >= N_EDGES) return;
    int s = ei[e];
    int d = ei[N_EDGES + e];
    int pos = atomicAdd(&g_cursor[d], 1);
    g_esrc[pos] = s;
}

// ---------------- atomic-free aggregation: warp per node ------------------------
template <bool BN>
__global__ void __launch_bounds__(256)
agg_kernel(const float* __restrict__ X, float* __restrict__ out,
           const float* __restrict__ scale, const float* __restrict__ shift) {
    int node = blockIdx.x * 8 + (threadIdx.x >> 5);
    int lane = threadIdx.x & 31;
    if (node >= N_NODES) return;
    int b0 = g_off[node], b1 = g_end[node];
    float4 sc, sh;
    if (BN) {
        sc = reinterpret_cast<const float4*>(scale)[lane];   // L1-resident
        sh = reinterpret_cast<const float4*>(shift)[lane];
    }
    float4 a0 = make_float4(0.f, 0.f, 0.f, 0.f);
    float4 a1 = a0, a2 = a0, a3 = a0;

    int i = b0;
    for (; i + 4 <= b1; i += 4) {
        int s0 = __ldcs(&g_esrc[i]);
        int s1 = __ldcs(&g_esrc[i + 1]);
        int s2 = __ldcs(&g_esrc[i + 2]);
        int s3 = __ldcs(&g_esrc[i + 3]);
        float4 v0 = reinterpret_cast<const float4*>(X + (size_t)s0 * F)[lane];
        float4 v1 = reinterpret_cast<const float4*>(X + (size_t)s1 * F)[lane];
        float4 v2 = reinterpret_cast<const float4*>(X + (size_t)s2 * F)[lane];
        float4 v3 = reinterpret_cast<const float4*>(X + (size_t)s3 * F)[lane];
        if (BN) {
            v0.x = fmaxf(v0.x * sc.x + sh.x, 0.f); v0.y = fmaxf(v0.y * sc.y + sh.y, 0.f);
            v0.z = fmaxf(v0.z * sc.z + sh.z, 0.f); v0.w = fmaxf(v0.w * sc.w + sh.w, 0.f);
            v1.x = fmaxf(v1.x * sc.x + sh.x, 0.f); v1.y = fmaxf(v1.y * sc.y + sh.y, 0.f);
            v1.z = fmaxf(v1.z * sc.z + sh.z, 0.f); v1.w = fmaxf(v1.w * sc.w + sh.w, 0.f);
            v2.x = fmaxf(v2.x * sc.x + sh.x, 0.f); v2.y = fmaxf(v2.y * sc.y + sh.y, 0.f);
            v2.z = fmaxf(v2.z * sc.z + sh.z, 0.f); v2.w = fmaxf(v2.w * sc.w + sh.w, 0.f);
            v3.x = fmaxf(v3.x * sc.x + sh.x, 0.f); v3.y = fmaxf(v3.y * sc.y + sh.y, 0.f);
            v3.z = fmaxf(v3.z * sc.z + sh.z, 0.f); v3.w = fmaxf(v3.w * sc.w + sh.w, 0.f);
        }
        a0.x += v0.x; a0.y += v0.y; a0.z += v0.z; a0.w += v0.w;
        a1.x += v1.x; a1.y += v1.y; a1.z += v1.z; a1.w += v1.w;
        a2.x += v2.x; a2.y += v2.y; a2.z += v2.z; a2.w += v2.w;
        a3.x += v3.x; a3.y += v3.y; a3.z += v3.z; a3.w += v3.w;
    }
    for (; i < b1; i++) {
        int s = __ldcs(&g_esrc[i]);
        float4 v = reinterpret_cast<const float4*>(X + (size_t)s * F)[lane];
        if (BN) {
            v.x = fmaxf(v.x * sc.x + sh.x, 0.f);
            v.y = fmaxf(v.y * sc.y + sh.y, 0.f);
            v.z = fmaxf(v.z * sc.z + sh.z, 0.f);
            v.w = fmaxf(v.w * sc.w + sh.w, 0.f);
        }
        a0.x += v.x; a0.y += v.y; a0.z += v.z; a0.w += v.w;
    }
    a0.x += a1.x + a2.x + a3.x;
    a0.y += a1.y + a2.y + a3.y;
    a0.z += a1.z + a2.z + a3.z;
    a0.w += a1.w + a2.w + a3.w;
    __stcs(reinterpret_cast<float4*>(out + (size_t)node * F) + lane, a0);
}

// ---------------- bf16 split helpers -------------------------------------------
__device__ __forceinline__ uint32_t pk2(__nv_bfloat16 a, __nv_bfloat16 b) {
    return (uint32_t)__bfloat16_as_ushort(b) << 16 | (uint32_t)__bfloat16_as_ushort(a);
}
__device__ __forceinline__ void split_pair(float x, float y,
                                           uint32_t& hi, uint32_t& lo) {
    __nv_bfloat16 hx = __float2bfloat16_rn(x);
    __nv_bfloat16 hy = __float2bfloat16_rn(y);
    float rx = x - __bfloat162float(hx);
    float ry = y - __bfloat162float(hy);
    hi = pk2(hx, hy);
    lo = pk2(__float2bfloat16_rn(rx), __float2bfloat16_rn(ry));
}

// ---------------- prep: pack all 4 W matrices into packed uint4 fragment tables -
__global__ void prep_w_all_kernel(const float* __restrict__ Wa,
                                  const float* __restrict__ Wb,
                                  const float* __restrict__ Wc,
                                  const float* __restrict__ Wd) {
    int gid   = blockIdx.x * blockDim.x + threadIdx.x;   // 0..16383
    int which = gid >> 12;
    int tid   = gid & 4095;
    const float* W = which == 0 ? Wa : which == 1 ? Wb : which == 2 ? Wc : Wd;
    int lane = tid & 31;
    int e    = tid >> 5;
    int nt   = e & 15;
    int kt   = e >> 4;
    int n  = nt * 8 + (lane >> 2);
    int k0 = kt * 16 + (lane & 3) * 2;
    uint32_t h0, l0, h1, l1;
    split_pair(W[k0 * 128 + n],       W[(k0 + 1) * 128 + n], h0, l0);
    split_pair(W[(k0 + 8) * 128 + n], W[(k0 + 9) * 128 + n], h1, l1);
    g_wtabP[which][tid] = make_uint4(h0, h1, l0, l1);
}

// ---------------- mma wrapper ---------------------------------------------------
__device__ __forceinline__ void mma_bf16(float c[4],
                                         uint32_t a0, uint32_t a1, uint32_t a2, uint32_t a3,
                                         uint32_t b0, uint32_t b1) {
    asm volatile(
        "mma.sync.aligned.m16n8k16.row.col.f32.bf16.bf16.f32 "
        "{%0,%1,%2,%3}, {%4,%5,%6,%7}, {%8,%9}, {%0,%1,%2,%3};"
        : "+f"(c[0]), "+f"(c[1]), "+f"(c[2]), "+f"(c[3])
        : "r"(a0), "r"(a1), "r"(a2), "r"(a3), "r"(b0), "r"(b1));
}

// ---------------- fused MLP (unchanged) -----------------------------------------
#define SA 68   // smem row stride in 32-bit words
#define MLP_SMEM (2 * 128 * SA * 4 + 256 * 4)   // A tiles + 256-float stats region
__global__ void __launch_bounds__(256, 2)
mlp_kernel(const float* __restrict__ Ain, const float* __restrict__ addSrc,
           const float* __restrict__ bnScale, const float* __restrict__ bnShift,
           float* __restrict__ C,
           const uint4* __restrict__ t1p, const uint4* __restrict__ t2p,
           const float* __restrict__ bias1, const float* __restrict__ bias2,
           float* __restrict__ gsum, float* __restrict__ gsq,
           int M) {
    extern __shared__ uint32_t sm[];
    uint32_t* Ahi = sm;                 // 128 * 68 words
    uint32_t* Alo = sm + 128 * SA;
    float*    Ssm = reinterpret_cast<float*>(sm + 2 * 128 * SA);  // [128] sums
    float*    Qsm = Ssm + 128;                                    // [128] sqs

    const int t    = threadIdx.x;
    const int lane = t & 31;
    const int w    = t >> 5;
    const int base = blockIdx.x * 128;

    if (t < 256) { Ssm[t] = 0.f; }   // zeros both Ssm and Qsm (256 contiguous)

    // ---- stage A tile: (Ain + addSrc[BN]) fp32 -> bf16 hi/lo smem --------------
    {
        int r    = t >> 1;            // row 0..127
        int half = t & 1;             // 64-col half
        int grow = base + r;
        bool valid = grow < M;
        const float4* src = valid
            ? reinterpret_cast<const float4*>(Ain + (size_t)grow * 128 + half * 64)
            : nullptr;
        const float4* add = valid
            ? reinterpret_cast<const float4*>(addSrc + (size_t)grow * 128 + half * 64)
            : nullptr;
        const float4* sc4 = bnScale
            ? reinterpret_cast<const float4*>(bnScale) + half * 16 : nullptr;
        const float4* sh4 = bnShift
            ? reinterpret_cast<const float4*>(bnShift) + half * 16 : nullptr;
        uint32_t* dh = Ahi + r * SA + half * 32;
        uint32_t* dl = Alo + r * SA + half * 32;
#pragma unroll
        for (int i = 0; i < 16; i++) {
            float4 v = make_float4(0.f, 0.f, 0.f, 0.f);
            if (valid) {
                float4 s = src[i];
                float4 a = add[i];
                if (sc4) {
                    float4 sc = sc4[i], sh = sh4[i];
                    a.x = fmaxf(a.x * sc.x + sh.x, 0.f);
                    a.y = fmaxf(a.y * sc.y + sh.y, 0.f);
                    a.z = fmaxf(a.z * sc.z + sh.z, 0.f);
                    a.w = fmaxf(a.w * sc.w + sh.w, 0.f);
                }
                v = make_float4(s.x + a.x, s.y + a.y, s.z + a.z, s.w + a.w);
            }
            uint32_t h0, l0, h1, l1;
            split_pair(v.x, v.y, h0, l0);
            split_pair(v.z, v.w, h1, l1);
            *reinterpret_cast<uint2*>(&dh[i * 2]) = make_uint2(h0, h1);
            *reinterpret_cast<uint2*>(&dl[i * 2]) = make_uint2(l0, l1);
        }
    }
    __syncthreads();

    const int g      = w >> 1;              // row group 0..3
    const int ntBase = (w & 1) * 8;         // column half
    const int mBase  = g * 32;
    const int ar0    = (mBase + (lane >> 2)) * SA + (lane & 3);  // rowtile 0 frag base
    const int ar1    = ar0 + 16 * SA;                            // rowtile 1

    float acc0[8][4], acc1[8][4];
#pragma unroll
    for (int nt = 0; nt < 8; nt++)
#pragma unroll
        for (int i = 0; i < 4; i++) { acc0[nt][i] = 0.f; acc1[nt][i] = 0.f; }

    // ================= GEMM 1 =================
#pragma unroll
    for (int kt = 0; kt < 8; kt++) {
        int wp0 = ar0 + kt * 8;
        int wp1 = ar1 + kt * 8;
        uint32_t xh0 = Ahi[wp0],     xh1 = Ahi[wp0 + 8 * SA];
        uint32_t xh2 = Ahi[wp0 + 4], xh3 = Ahi[wp0 + 8 * SA + 4];
        uint32_t xl0 = Alo[wp0],     xl1 = Alo[wp0 + 8 * SA];
        uint32_t xl2 = Alo[wp0 + 4], xl3 = Alo[wp0 + 8 * SA + 4];
        uint32_t yh0 = Ahi[wp1],     yh1 = Ahi[wp1 + 8 * SA];
        uint32_t yh2 = Ahi[wp1 + 4], yh3 = Ahi[wp1 + 8 * SA + 4];
        uint32_t yl0 = Alo[wp1],     yl1 = Alo[wp1 + 8 * SA];
        uint32_t yl2 = Alo[wp1 + 4], yl3 = Alo[wp1 + 8 * SA + 4];
#pragma unroll
        for (int nt = 0; nt < 8; nt++) {
            uint4 b = t1p[(kt * 16 + ntBase + nt) * 32 + lane];
            mma_bf16(acc0[nt], xh0, xh1, xh2, xh3, b.x, b.y);   // hi*hi
            mma_bf16(acc1[nt], yh0, yh1, yh2, yh3, b.x, b.y);
            mma_bf16(acc0[nt], xh0, xh1, xh2, xh3, b.z, b.w);   // hi*lo
            mma_bf16(acc1[nt], yh0, yh1, yh2, yh3, b.z, b.w);
            mma_bf16(acc0[nt], xl0, xl1, xl2, xl3, b.x, b.y);   // lo*hi
            mma_bf16(acc1[nt], yl0, yl1, yl2, yl3, b.x, b.y);
        }
    }
    __syncthreads();

    // ---- mid epilogue: bias1 + relu, re-split t1 into the same smem tile ----
#pragma unroll
    for (int nt = 0; nt < 8; nt++) {
        int ntg = ntBase + nt;
        int n0  = ntg * 8 + (lane & 3) * 2;
        float bb0 = bias1[n0], bb1 = bias1[n0 + 1];
        int word0 = (mBase + (lane >> 2)) * SA + ntg * 4 + (lane & 3);
#pragma unroll
        for (int rt = 0; rt < 2; rt++) {
            float (&a)[4] = rt ? acc1[nt] : acc0[nt];
            int word = word0 + rt * 16 * SA;
            float v0 = fmaxf(a[0] + bb0, 0.f);
            float v1 = fmaxf(a[1] + bb1, 0.f);
            float v2 = fmaxf(a[2] + bb0, 0.f);
            float v3 = fmaxf(a[3] + bb1, 0.f);
            uint32_t h, l;
            split_pair(v0, v1, h, l);
            Ahi[word] = h;  Alo[word] = l;
            split_pair(v2, v3, h, l);
            Ahi[word + 8 * SA] = h;  Alo[word + 8 * SA] = l;
            a[0] = a[1] = a[2] = a[3] = 0.f;
        }
    }
    __syncthreads();

    // ================= GEMM 2 =================
#pragma unroll
    for (int kt = 0; kt < 8; kt++) {
        int wp0 = ar0 + kt * 8;
        int wp1 = ar1 + kt * 8;
        uint32_t xh0 = Ahi[wp0],     xh1 = Ahi[wp0 + 8 * SA];
        uint32_t xh2 = Ahi[wp0 + 4], xh3 = Ahi[wp0 + 8 * SA + 4];
        uint32_t xl0 = Alo[wp0],     xl1 = Alo[wp0 + 8 * SA];
        uint32_t xl2 = Alo[wp0 + 4], xl3 = Alo[wp0 + 8 * SA + 4];
        uint32_t yh0 = Ahi[wp1],     yh1 = Ahi[wp1 + 8 * SA];
        uint32_t yh2 = Ahi[wp1 + 4], yh3 = Ahi[wp1 + 8 * SA + 4];
        uint32_t yl0 = Alo[wp1],     yl1 = Alo[wp1 + 8 * SA];
        uint32_t yl2 = Alo[wp1 + 4], yl3 = Alo[wp1 + 8 * SA + 4];
#pragma unroll
        for (int nt = 0; nt < 8; nt++) {
            uint4 b = t2p[(kt * 16 + ntBase + nt) * 32 + lane];
            mma_bf16(acc0[nt], xh0, xh1, xh2, xh3, b.x, b.y);
            mma_bf16(acc1[nt], yh0, yh1, yh2, yh3, b.x, b.y);
            mma_bf16(acc0[nt], xh0, xh1, xh2, xh3, b.z, b.w);
            mma_bf16(acc1[nt], yh0, yh1, yh2, yh3, b.z, b.w);
            mma_bf16(acc0[nt], xl0, xl1, xl2, xl3, b.x, b.y);
            mma_bf16(acc1[nt], yl0, yl1, yl2, yl3, b.x, b.y);
        }
    }

    // ---- final epilogue: bias2, fp32 store, fused per-column BN statistics ----
#pragma unroll
    for (int nt = 0; nt < 8; nt++) {
        int ntg = ntBase + nt;
        int n0  = ntg * 8 + (lane & 3) * 2;
        float bb0 = bias2[n0], bb1 = bias2[n0 + 1];
        float S0 = 0.f, S1 = 0.f, Q0 = 0.f, Q1 = 0.f;
#pragma unroll
        for (int rt = 0; rt < 2; rt++) {
            float (&a)[4] = rt ? acc1[nt] : acc0[nt];
            int row0 = base + mBase + rt * 16 + (lane >> 2);
            bool r0v = row0 < M, r1v = (row0 + 8) < M;
            float v0 = a[0] + bb0, v1 = a[1] + bb1;
            float v2 = a[2] + bb0, v3 = a[3] + bb1;
            if (r0v)
                *reinterpret_cast<float2*>(C + (size_t)row0 * 128 + n0) = make_float2(v0, v1);
            if (r1v)
                *reinterpret_cast<float2*>(C + (size_t)(row0 + 8) * 128 + n0) = make_float2(v2, v3);
            S0 += (r0v ? v0 : 0.f) + (r1v ? v2 : 0.f);
            S1 += (r0v ? v1 : 0.f) + (r1v ? v3 : 0.f);
            Q0 += (r0v ? v0 * v0 : 0.f) + (r1v ? v2 * v2 : 0.f);
            Q1 += (r0v ? v1 * v1 : 0.f) + (r1v ? v3 * v3 : 0.f);
        }
#pragma unroll
        for (int o = 4; o < 32; o <<= 1) {
            S0 += __shfl_xor_sync(0xffffffffu, S0, o);
            S1 += __shfl_xor_sync(0xffffffffu, S1, o);
            Q0 += __shfl_xor_sync(0xffffffffu, Q0, o);
            Q1 += __shfl_xor_sync(0xffffffffu, Q1, o);
        }
        if ((lane >> 2) == 0) {   // lanes 0..3, distinct n0 per lane
            atomicAdd(&Ssm[n0], S0);     atomicAdd(&Ssm[n0 + 1], S1);
            atomicAdd(&Qsm[n0], Q0);     atomicAdd(&Qsm[n0 + 1], Q1);
        }
    }
    __syncthreads();
    if (t < 128) {
        atomicAdd(&gsum[t], Ssm[t]);
        atomicAdd(&gsq[t],  Qsm[t]);
    }
}

// ---------------- BN coefficient computation (1 block, 128 threads) -------------
__global__ void bn_coef_kernel(const float* __restrict__ sum,
                               const float* __restrict__ sq,
                               const float* __restrict__ gamma,
                               const float* __restrict__ beta,
                               float* __restrict__ scale,
                               float* __restrict__ shift) {
    int c = threadIdx.x;
    const float invN = 1.0f / (float)N_NODES;
    float mean = sum[c] * invN;
    float var  = fmaxf(sq[c] * invN - mean * mean, 0.f);
    float sc   = gamma[c] * rsqrtf(var + BN_EPS);
    scale[c] = sc;
    shift[c] = beta[c] - mean * sc;
}

// ---------------- fused BN2 + ReLU + segmented pool + counts (batch sorted) -----
#define POOL_CHUNK 128
__global__ void pool_kernel(const float* __restrict__ H,
                            const float* __restrict__ scale,
                            const float* __restrict__ shift,
                            const int* __restrict__ batch) {
    const int c = threadIdx.x;   // blockDim = 128
    float sc = scale[c], sh = shift[c];

    int r0 = blockIdx.x * POOL_CHUNK;
    if (r0 >= N_NODES) return;
    int r1 = min(r0 + POOL_CHUNK, N_NODES);

    int g = batch[r0];
    float acc = 0.f;
    int cnt = 0;
    for (int r = r0; r < r1; r++) {
        int gg = batch[r];
        if (gg != g) {
            atomicAdd(&g_pooled[g * F + c], acc);
            if (c == 0) atomicAdd(&g_counts[g], (float)cnt);
            acc = 0.f; cnt = 0; g = gg;
        }
        acc += fmaxf(H[(size_t)r * F + c] * sc + sh, 0.f);
        cnt++;
    }
    atomicAdd(&g_pooled[g * F + c], acc);
    if (c == 0) atomicAdd(&g_counts[g], (float)cnt);
}

// ---------------- head: mean-pool divide + linear + log_softmax ----------------
__global__ void head_kernel(const float* __restrict__ Wlin,
                            const float* __restrict__ blin,
                            float* __restrict__ out) {
    __shared__ float Ws[F * NUM_CLASSES];
    int t = threadIdx.x;   // blockDim = 128, one thread per graph
    for (int i = t; i < F * NUM_CLASSES; i += 128) Ws[i] = Wlin[i];
    __syncthreads();

    int g = t;
    float inv = 1.0f / fmaxf(g_counts[g], 1.0f);
    float logit[NUM_CLASSES];
#pragma unroll
    for (int j = 0; j < NUM_CLASSES; j++) logit[j] = blin[j];
    for (int c = 0; c < F; c++) {
        float p = g_pooled[g * F + c] * inv;
#pragma unroll
        for (int j = 0; j < NUM_CLASSES; j++)
            logit[j] += p * Ws[c * NUM_CLASSES + j];
    }
    float m = logit[0];
#pragma unroll
    for (int j = 1; j < NUM_CLASSES; j++) m = fmaxf(m, logit[j]);
    float se = 0.f;
#pragma unroll
    for (int j = 0; j < NUM_CLASSES; j++) se += expf(logit[j] - m);
    float lse = logf(se);
#pragma unroll
    for (int j = 0; j < NUM_CLASSES; j++)
        out[g * NUM_CLASSES + j] = logit[j] - m - lse;
}

// ================================================================================
extern "C" void kernel_launch(void* const* d_in, const int* in_sizes, int n_in,
                              void* d_out, int out_size) {
    const float* x     = (const float*)d_in[0];
    const int*   ei    = (const int*)d_in[1];
    const int*   batch = (const int*)d_in[2];
    const float* W1a = (const float*)d_in[3];
    const float* b1a = (const float*)d_in[4];
    const float* W1b = (const float*)d_in[5];
    const float* b1b = (const float*)d_in[6];
    const float* gamma1 = (const float*)d_in[7];
    const float* beta1  = (const float*)d_in[8];
    const float* W2a = (const float*)d_in[9];
    const float* b2a = (const float*)d_in[10];
    const float* W2b = (const float*)d_in[11];
    const float* b2b = (const float*)d_in[12];
    const float* gamma2 = (const float*)d_in[13];
    const float* beta2  = (const float*)d_in[14];
    const float* Wlin = (const float*)d_in[15];
    const float* blin = (const float*)d_in[16];
    float* out = (float*)d_out;

    float *pA, *pB, *pC, *pSum1, *pSq1, *pSum2, *pSq2;
    float *pScale1, *pShift1, *pScale2, *pShift2;
    uint4 *pWP;
    cudaGetSymbolAddress((void**)&pA, g_bufA);
    cudaGetSymbolAddress((void**)&pB, g_bufB);
    cudaGetSymbolAddress((void**)&pC, g_bufC);
    cudaGetSymbolAddress((void**)&pSum1, g_sum1);
    cudaGetSymbolAddress((void**)&pSq1,  g_sq1);
    cudaGetSymbolAddress((void**)&pSum2, g_sum2);
    cudaGetSymbolAddress((void**)&pSq2,  g_sq2);
    cudaGetSymbolAddress((void**)&pScale1, g_scale1);
    cudaGetSymbolAddress((void**)&pShift1, g_shift1);
    cudaGetSymbolAddress((void**)&pScale2, g_scale2);
    cudaGetSymbolAddress((void**)&pShift2, g_shift2);
    cudaGetSymbolAddress((void**)&pWP, g_wtabP);

    static int smem_set = 0;
    if (!smem_set) {
        cudaFuncSetAttribute(mlp_kernel,
                             cudaFuncAttributeMaxDynamicSharedMemorySize, MLP_SMEM);
        smem_set = 1;
    }

    const int M = N_NODES;
    const int mlpBlocks = (M + 127) / 128;
    const int edgeBlocks = (N_EDGES + 255) / 256;
    const int aggBlocks = (N_NODES + 7) / 8;

    // build CSR-by-destination (3 kernels)
    hist_kernel<<<edgeBlocks, 256>>>(ei);                  // launch 1 (resets gcnt)
    scanF_kernel<<<SCAN_NB, SCAN_BLK>>>();                 // launch 2 (zeroes hist)
    reorder_kernel<<<edgeBlocks, 256>>>(ei);               // launch 3

    // ---- layer 1: agg1 = sum_neighbors(x) -> bufA (launch 4: ncu-captured)
    agg_kernel<false><<<aggBlocks, 256>>>(x, pA, nullptr, nullptr);

    // prep: zero accumulators + pack weight tables (before mlp1)
    zero_small_kernel<<<64, 256>>>();
    prep_w_all_kernel<<<64, 256>>>(W1a, W1b, W2a, W2b);

    // MLP1 adds +x during staging
    mlp_kernel<<<mlpBlocks, 256, MLP_SMEM>>>(
        pA, x, nullptr, nullptr, pA,
        pWP + 0 * 4096, pWP + 1 * 4096,
        b1a, b1b, pSum1, pSq1, M);
    bn_coef_kernel<<<1, 128>>>(pSum1, pSq1, gamma1, beta1, pScale1, pShift1);

    // ---- layer 2: agg2 = sum_neighbors(BN1(h1)) -> bufC ; MLP2 adds +BN1(h1)
    agg_kernel<true><<<aggBlocks, 256>>>(pA, pC, pScale1, pShift1);
    mlp_kernel<<<mlpBlocks, 256, MLP_SMEM>>>(
        pC, pA, pScale1, pShift1, pB,
        pWP + 2 * 4096, pWP + 3 * 4096,
        b2a, b2b, pSum2, pSq2, M);
    bn_coef_kernel<<<1, 128>>>(pSum2, pSq2, gamma2, beta2, pScale2, pShift2);

    // ---- pooling (BN2+ReLU on the fly, fused counts) + head
    pool_kernel<<<(N_NODES + POOL_CHUNK - 1) / POOL_CHUNK, 128>>>(
        pB, pScale2, pShift2, batch);
    head_kernel<<<1, 128>>>(Wlin, blin, out);
}